// round 12
// baseline (speedup 1.0000x reference)
#include <cuda_runtime.h>
#include <cuda_fp16.h>
#include <math.h>
#include <stdint.h>

#define D_MODEL 1024
#define D_FF    1024
#define NE      8
#define NTOK    8192
#define NPAIRS  16384
#define BM      128
#define BN      128
#define NKT     32

// ---------------------------------------------------------------------------
// Static scratch (single fp16 everywhere)
// ---------------------------------------------------------------------------
__device__ __half d_x[(size_t)NTOK * D_MODEL];
__device__ __half d_wg[(size_t)NE * D_FF * D_MODEL];
__device__ __half d_wu[(size_t)NE * D_FF * D_MODEL];
__device__ __half d_wd[(size_t)NE * D_MODEL * D_FF];
__device__ __half d_act[(size_t)NPAIRS * D_FF];
__device__ int   d_list[NE * NTOK];
__device__ int   d_cnt[NE];
__device__ float d_wgt[NPAIRS];
__device__ float d_probs[NTOK * NE];
__device__ float d_auxp[32 * NE];

// ---------------------------------------------------------------------------
// Helpers (generic PTX only)
// ---------------------------------------------------------------------------
__device__ __forceinline__ uint32_t smem_u32(const void* p) {
    uint32_t a;
    asm("{ .reg .u64 t; cvta.to.shared.u64 t, %1; cvt.u32.u64 %0, t; }" : "=r"(a) : "l"(p));
    return a;
}
__device__ __forceinline__ void cp16(uint32_t dst, const void* src) {
    asm volatile("cp.async.cg.shared.global [%0], [%1], 16;" :: "r"(dst), "l"(src));
}
#define CP_COMMIT() asm volatile("cp.async.commit_group;" ::: "memory")
#define CP_WAIT2()  asm volatile("cp.async.wait_group 2;" ::: "memory")

// Conflict-free swizzle for 64B rows of 16B chunks.
#define SWZ(r, c) ((uint32_t)((r) * 64 + (((c) ^ (((r) >> 1) & 3)) << 4)))

__device__ __forceinline__ void ldmA(uint32_t r[4], uint32_t addr) {
    asm volatile("ldmatrix.sync.aligned.m8n8.x4.shared.b16 {%0,%1,%2,%3}, [%4];"
                 : "=r"(r[0]), "=r"(r[1]), "=r"(r[2]), "=r"(r[3]) : "r"(addr));
}
__device__ __forceinline__ void ldmB(uint32_t r[2], uint32_t addr) {
    asm volatile("ldmatrix.sync.aligned.m8n8.x2.shared.b16 {%0,%1}, [%2];"
                 : "=r"(r[0]), "=r"(r[1]) : "r"(addr));
}
__device__ __forceinline__ void mma16816(float d[4], const uint32_t a[4], const uint32_t b[2]) {
    asm volatile("mma.sync.aligned.m16n8k16.row.col.f32.f16.f16.f32 "
                 "{%0,%1,%2,%3}, {%4,%5,%6,%7}, {%8,%9}, {%0,%1,%2,%3};"
                 : "+f"(d[0]), "+f"(d[1]), "+f"(d[2]), "+f"(d[3])
                 : "r"(a[0]), "r"(a[1]), "r"(a[2]), "r"(a[3]), "r"(b[0]), "r"(b[1]));
}
__device__ __forceinline__ uint32_t pack_h(__half a, __half b) {
    return (uint32_t)__half_as_ushort(a) | ((uint32_t)__half_as_ushort(b) << 16);
}
__device__ __forceinline__ float silu_mul(float g, float u) {
    return (g / (1.f + __expf(-g))) * u;
}

// ---------------------------------------------------------------------------
// Conversion + init fused: regions 0-2 = weights->fp16, region 3 = zero out.
// Also zeroes d_cnt (runs fully before router on the same stream).
// ---------------------------------------------------------------------------
struct ConvArgs {
    const float* src[3];
    __half* dst[3];
    float* out;
};

__global__ void conv4_kernel(ConvArgs a) {
    const int gid = blockIdx.x * blockDim.x + threadIdx.x;
    if (gid < NE) d_cnt[gid] = 0;
    const int total = 4 << 21;
    for (int i = gid; i < total; i += gridDim.x * blockDim.x) {
        const int reg = i >> 21;
        const int off = i & ((1 << 21) - 1);
        if (reg < 3) {
            float4 v = ((const float4*)a.src[reg])[off];
            uint32_t* h2 = (uint32_t*)a.dst[reg];
            h2[2 * off + 0] = pack_h(__float2half(v.x), __float2half(v.y));
            h2[2 * off + 1] = pack_h(__float2half(v.z), __float2half(v.w));
        } else {
            ((float4*)a.out)[off] = make_float4(0.f, 0.f, 0.f, 0.f);
        }
    }
}

// ---------------------------------------------------------------------------
// Router: logits/softmax/top-2 + emits x row as fp16 (saves a conv region)
// ---------------------------------------------------------------------------
__global__ void router_kernel(const float* __restrict__ x, const float* __restrict__ gw) {
    const int lane = threadIdx.x & 31;
    const int warp = threadIdx.x >> 5;
    const int t = blockIdx.x * (blockDim.x >> 5) + warp;
    if (t >= NTOK) return;

    const float4* xp = (const float4*)(x + (size_t)t * D_MODEL);
    float4 xv[8];
#pragma unroll
    for (int i = 0; i < 8; i++) xv[i] = xp[i * 32 + lane];

    // fp16 conversion of the token row (from registers)
    uint2* xo = (uint2*)(d_x + (size_t)t * D_MODEL);
#pragma unroll
    for (int i = 0; i < 8; i++)
        xo[i * 32 + lane] = make_uint2(pack_h(__float2half(xv[i].x), __float2half(xv[i].y)),
                                       pack_h(__float2half(xv[i].z), __float2half(xv[i].w)));

    float logit[NE];
#pragma unroll
    for (int e = 0; e < NE; e++) {
        const float4* gp = (const float4*)(gw + e * D_MODEL);
        float s = 0.f;
#pragma unroll
        for (int i = 0; i < 8; i++) {
            float4 g = gp[i * 32 + lane];
            s += xv[i].x * g.x + xv[i].y * g.y + xv[i].z * g.z + xv[i].w * g.w;
        }
#pragma unroll
        for (int o = 16; o > 0; o >>= 1) s += __shfl_xor_sync(0xffffffffu, s, o);
        logit[e] = s;
    }

    if (lane == 0) {
        float m = logit[0];
#pragma unroll
        for (int e = 1; e < NE; e++) m = fmaxf(m, logit[e]);
        float p[NE], sum = 0.f;
#pragma unroll
        for (int e = 0; e < NE; e++) { p[e] = expf(logit[e] - m); sum += p[e]; }
        const float inv = 1.f / sum;
#pragma unroll
        for (int e = 0; e < NE; e++) { p[e] *= inv; d_probs[t * NE + e] = p[e]; }

        int i0 = 0;
#pragma unroll
        for (int e = 1; e < NE; e++) if (p[e] > p[i0]) i0 = e;
        int i1 = (i0 == 0) ? 1 : 0;
#pragma unroll
        for (int e = 0; e < NE; e++) if (e != i0 && p[e] > p[i1]) i1 = e;

        const float s2 = p[i0] + p[i1];
        int pos0 = atomicAdd(&d_cnt[i0], 1);
        d_list[i0 * NTOK + pos0] = 2 * t;
        d_wgt[2 * t] = p[i0] / s2;
        int pos1 = atomicAdd(&d_cnt[i1], 1);
        d_list[i1 * NTOK + pos1] = 2 * t + 1;
        d_wgt[2 * t + 1] = p[i1] / s2;
    }
}

// ---------------------------------------------------------------------------
// Aux loss: 32-block partials + finalize (fixed-order, deterministic)
// ---------------------------------------------------------------------------
__global__ void aux_part_kernel() {
    __shared__ float s[256][NE];
    const int tid = threadIdx.x;
    const int t = blockIdx.x * 256 + tid;
#pragma unroll
    for (int e = 0; e < NE; e++) s[tid][e] = d_probs[t * NE + e];
    __syncthreads();
    const int w = tid >> 5, lane = tid & 31;
    if (w < NE) {
        float v = 0.f;
        for (int i = lane; i < 256; i += 32) v += s[i][w];
#pragma unroll
        for (int o = 16; o > 0; o >>= 1) v += __shfl_xor_sync(0xffffffffu, v, o);
        if (lane == 0) d_auxp[blockIdx.x * NE + w] = v;
    }
}

__global__ void aux_fin_kernel(float* __restrict__ out) {
    const int tid = threadIdx.x;
    __shared__ float ps[NE];
    if (tid < NE) {
        float v = 0.f;
        for (int b = 0; b < 32; b++) v += d_auxp[b * NE + tid];
        ps[tid] = v;
        out[(size_t)NTOK * D_MODEL + 1 + tid] = (float)d_cnt[tid];
    }
    __syncthreads();
    if (tid == 0) {
        float aux = 0.f;
        for (int e = 0; e < NE; e++)
            aux += ((float)d_cnt[e] * (1.f / (float)NPAIRS)) * (ps[e] * (1.f / (float)NTOK));
        out[(size_t)NTOK * D_MODEL] = (float)NE * aux;
    }
}

// ---------------------------------------------------------------------------
// GEMM1 fused: g = x@wg^T, u = x@wu^T; single fp16; act = silu(g)*u.
// 256 threads, 2x4 warp grid, 64x32 warp tiles per matrix, 4-stage pipeline.
// Stage (24KB): A(8K) G(8K) U(8K)
// ---------------------------------------------------------------------------
#define G1_STAGES 4
#define G1_STG  24576
#define G1_SMEM (1024 + G1_STAGES * G1_STG)

__device__ __forceinline__ void g1_issue(int tid, const int* plist,
                                         const __half* gw_, const __half* uw_,
                                         int n0, int kt, uint32_t base) {
#pragma unroll
    for (int q = 0; q < 2; q++) {
        const int id = tid + q * 256;
        const int r = id >> 2, c = id & 3;
        const uint32_t sw = SWZ(r, c);
        const size_t aoff = (size_t)(plist[r] >> 1) * (D_MODEL * 2) + kt * 64 + c * 16;
        const size_t boff = (size_t)(n0 + r) * (D_MODEL * 2) + kt * 64 + c * 16;
        cp16(base + sw,         (const char*)d_x + aoff);
        cp16(base + 8192 + sw,  (const char*)gw_ + boff);
        cp16(base + 16384 + sw, (const char*)uw_ + boff);
    }
}

__global__ __launch_bounds__(256, 1) void gemm1_kernel() {
    const int e = blockIdx.z;
    const int cnt = d_cnt[e];
    const int m0 = blockIdx.x * BM;
    if (m0 >= cnt) return;
    const int n0 = blockIdx.y * BN;

    extern __shared__ __align__(128) char smem[];
    const uint32_t sb = smem_u32(smem);
    const int tid = threadIdx.x;
    const int lane = tid & 31;
    const int w = tid >> 5;
    const int wm = w >> 2, wn = w & 3;   // wm 0..1 (64-row slabs), wn 0..3 (32-col)
    const int rows = min(BM, cnt - m0);

    int* s_plist = (int*)smem;
    if (tid < BM) s_plist[tid] = (tid < rows) ? d_list[e * NTOK + m0 + tid] : 0;
    __syncthreads();

    const __half* gw_ = d_wg + ((size_t)e << 20);
    const __half* uw_ = d_wu + ((size_t)e << 20);

    g1_issue(tid, s_plist, gw_, uw_, n0, 0, sb + 1024);
    CP_COMMIT();
    g1_issue(tid, s_plist, gw_, uw_, n0, 1, sb + 1024 + G1_STG);
    CP_COMMIT();
    g1_issue(tid, s_plist, gw_, uw_, n0, 2, sb + 1024 + 2 * G1_STG);
    CP_COMMIT();

    float dg[4][4][4], du[4][4][4];
#pragma unroll
    for (int i = 0; i < 4; i++)
#pragma unroll
        for (int j = 0; j < 4; j++)
#pragma unroll
            for (int k = 0; k < 4; k++) { dg[i][j][k] = 0.f; du[i][j][k] = 0.f; }

    for (int kt = 0; kt < NKT; kt++) {
        CP_WAIT2();
        __syncthreads();
        if (kt + 3 < NKT)
            g1_issue(tid, s_plist, gw_, uw_, n0,
                     kt + 3, sb + 1024 + ((kt + 3) % G1_STAGES) * G1_STG);
        CP_COMMIT();

        const uint32_t st = sb + 1024 + (kt % G1_STAGES) * G1_STG;
#pragma unroll
        for (int ks = 0; ks < 2; ks++) {
            uint32_t ah[4][4];
#pragma unroll
            for (int i = 0; i < 4; i++) {
                const int row = wm * 64 + i * 16 + (lane & 15);
                const int ch = ks * 2 + (lane >> 4);
                ldmA(ah[i], st + SWZ(row, ch));
            }
            uint32_t bg[4][2], bu[4][2];
#pragma unroll
            for (int j = 0; j < 4; j++) {
                const int row = wn * 32 + j * 8 + (lane & 7);
                const int ch = ks * 2 + ((lane >> 3) & 1);
                const uint32_t off = SWZ(row, ch);
                ldmB(bg[j], st + 8192 + off);
                ldmB(bu[j], st + 16384 + off);
            }
#pragma unroll
            for (int i = 0; i < 4; i++)
#pragma unroll
                for (int j = 0; j < 4; j++) mma16816(dg[i][j], ah[i], bg[j]);
#pragma unroll
            for (int i = 0; i < 4; i++)
#pragma unroll
                for (int j = 0; j < 4; j++) mma16816(du[i][j], ah[i], bu[j]);
        }
        __syncthreads();
    }

    // Epilogue: act = silu(g)*u -> fp16
    const int r0 = lane >> 2;
    const int c0 = (lane & 3) * 2;
#pragma unroll
    for (int i = 0; i < 4; i++) {
        const int mA = wm * 64 + i * 16 + r0;
        const int mB = mA + 8;
        const int pidA = s_plist[mA & 127];
        const int pidB = s_plist[mB & 127];
#pragma unroll
        for (int j = 0; j < 4; j++) {
            const int col = n0 + wn * 32 + j * 8 + c0;
            if (mA < rows) {
                *(uint32_t*)(d_act + (size_t)pidA * D_FF + col) =
                    pack_h(__float2half(silu_mul(dg[i][j][0], du[i][j][0])),
                           __float2half(silu_mul(dg[i][j][1], du[i][j][1])));
            }
            if (mB < rows) {
                *(uint32_t*)(d_act + (size_t)pidB * D_FF + col) =
                    pack_h(__float2half(silu_mul(dg[i][j][2], du[i][j][2])),
                           __float2half(silu_mul(dg[i][j][3], du[i][j][3])));
            }
        }
    }
}

// ---------------------------------------------------------------------------
// GEMM2: out += w * (act @ wd^T); single fp16. 256 threads, 64x32 warp tiles,
// 4-stage pipeline, 2 CTAs/SM, float2 atomics. (unchanged from R8)
// ---------------------------------------------------------------------------
#define G2_STAGES 4
#define G2_STG  16384
#define G2_SMEM (1024 + G2_STAGES * G2_STG)

__device__ __forceinline__ void g2_issue(int tid, const int* plist,
                                         const __half* bw, int n0, int kt, uint32_t base) {
#pragma unroll
    for (int q = 0; q < 2; q++) {
        const int id = tid + q * 256;
        const int r = id >> 2, c = id & 3;
        const uint32_t sw = SWZ(r, c);
        const size_t aoff = (size_t)plist[r] * (D_FF * 2) + kt * 64 + c * 16;
        const size_t boff = (size_t)(n0 + r) * (D_FF * 2) + kt * 64 + c * 16;
        cp16(base + sw,        (const char*)d_act + aoff);
        cp16(base + 8192 + sw, (const char*)bw + boff);
    }
}

__global__ __launch_bounds__(256, 2) void gemm2_kernel(float* __restrict__ out) {
    const int e = blockIdx.z;
    const int cnt = d_cnt[e];
    const int m0 = blockIdx.x * BM;
    if (m0 >= cnt) return;
    const int n0 = blockIdx.y * BN;

    extern __shared__ __align__(128) char smem[];
    const uint32_t sb = smem_u32(smem);
    const int tid = threadIdx.x;
    const int lane = tid & 31;
    const int w = tid >> 5;
    const int wm = w >> 2, wn = w & 3;
    const int rows = min(BM, cnt - m0);

    int* s_plist = (int*)smem;
    if (tid < BM) s_plist[tid] = (tid < rows) ? d_list[e * NTOK + m0 + tid] : 0;
    __syncthreads();

    const __half* bw = d_wd + ((size_t)e << 20);

    g2_issue(tid, s_plist, bw, n0, 0, sb + 1024);
    CP_COMMIT();
    g2_issue(tid, s_plist, bw, n0, 1, sb + 1024 + G2_STG);
    CP_COMMIT();
    g2_issue(tid, s_plist, bw, n0, 2, sb + 1024 + 2 * G2_STG);
    CP_COMMIT();

    float dd[4][4][4];
#pragma unroll
    for (int i = 0; i < 4; i++)
#pragma unroll
        for (int j = 0; j < 4; j++)
#pragma unroll
            for (int k = 0; k < 4; k++) dd[i][j][k] = 0.f;

    for (int kt = 0; kt < NKT; kt++) {
        CP_WAIT2();
        __syncthreads();
        if (kt + 3 < NKT)
            g2_issue(tid, s_plist, bw, n0, kt + 3,
                     sb + 1024 + ((kt + 3) % G2_STAGES) * G2_STG);
        CP_COMMIT();

        const uint32_t st = sb + 1024 + (kt % G2_STAGES) * G2_STG;
#pragma unroll
        for (int ks = 0; ks < 2; ks++) {
            uint32_t ah[4][4];
#pragma unroll
            for (int i = 0; i < 4; i++) {
                const int row = wm * 64 + i * 16 + (lane & 15);
                const int ch = ks * 2 + (lane >> 4);
                ldmA(ah[i], st + SWZ(row, ch));
            }
#pragma unroll
            for (int j = 0; j < 4; j++) {
                const int row = wn * 32 + j * 8 + (lane & 7);
                const int ch = ks * 2 + ((lane >> 3) & 1);
                uint32_t fb[2];
                ldmB(fb, st + 8192 + SWZ(row, ch));
#pragma unroll
                for (int i = 0; i < 4; i++) mma16816(dd[i][j], ah[i], fb);
            }
        }
        __syncthreads();
    }

    // Weighted deterministic scatter: float2 atomics (2 adds/element total)
    const int r0 = lane >> 2;
    const int c0 = (lane & 3) * 2;
#pragma unroll
    for (int i = 0; i < 4; i++) {
        const int mA = wm * 64 + i * 16 + r0;
        const int mB = mA + 8;
        const int pidA = s_plist[mA & 127];
        const int pidB = s_plist[mB & 127];
        const float wA = d_wgt[pidA];
        const float wB = d_wgt[pidB];
#pragma unroll
        for (int j = 0; j < 4; j++) {
            const int col = n0 + wn * 32 + j * 8 + c0;
            if (mA < rows) {
                float2* p = (float2*)(out + (size_t)(pidA >> 1) * D_MODEL + col);
                atomicAdd(p, make_float2(wA * dd[i][j][0], wA * dd[i][j][1]));
            }
            if (mB < rows) {
                float2* p = (float2*)(out + (size_t)(pidB >> 1) * D_MODEL + col);
                atomicAdd(p, make_float2(wB * dd[i][j][2], wB * dd[i][j][3]));
            }
        }
    }
}

// ---------------------------------------------------------------------------
// Launch
// ---------------------------------------------------------------------------
extern "C" void kernel_launch(void* const* d_in, const int* in_sizes, int n_in,
                              void* d_out, int out_size) {
    const float* x  = (const float*)d_in[0];
    const float* gw = (const float*)d_in[1];
    const float* wg = (const float*)d_in[2];
    const float* wu = (const float*)d_in[3];
    const float* wd = (const float*)d_in[4];
    float* out = (float*)d_out;

    cudaFuncSetAttribute(gemm1_kernel, cudaFuncAttributeMaxDynamicSharedMemorySize, G1_SMEM);
    cudaFuncSetAttribute(gemm2_kernel, cudaFuncAttributeMaxDynamicSharedMemorySize, G2_SMEM);

    ConvArgs ca;
    ca.src[0] = wg; ca.src[1] = wu; ca.src[2] = wd;
    cudaGetSymbolAddress((void**)&ca.dst[0], d_wg);
    cudaGetSymbolAddress((void**)&ca.dst[1], d_wu);
    cudaGetSymbolAddress((void**)&ca.dst[2], d_wd);
    ca.out = out;

    conv4_kernel<<<4736, 256>>>(ca);
    router_kernel<<<NTOK / 8, 256>>>(x, gw);
    aux_part_kernel<<<32, 256>>>();
    aux_fin_kernel<<<1, 64>>>(out);
    gemm1_kernel<<<dim3(64, 8, 8), 256, G1_SMEM>>>();
    gemm2_kernel<<<dim3(64, 8, 8), 256, G2_SMEM>>>(out);
}

// round 17
// speedup vs baseline: 1.0807x; 1.0807x over previous
#include <cuda_runtime.h>
#include <cuda_fp16.h>
#include <math.h>
#include <stdint.h>

#define D_MODEL 1024
#define D_FF    1024
#define NE      8
#define NTOK    8192
#define NPAIRS  16384
#define BM      128
#define BN      128
#define NKT     32

// ---------------------------------------------------------------------------
// Static scratch (single fp16 everywhere)
// ---------------------------------------------------------------------------
__device__ __half d_x[(size_t)NTOK * D_MODEL];
__device__ __half d_wg[(size_t)NE * D_FF * D_MODEL];
__device__ __half d_wu[(size_t)NE * D_FF * D_MODEL];
__device__ __half d_wd[(size_t)NE * D_MODEL * D_FF];
__device__ __half d_act[(size_t)NPAIRS * D_FF];
__device__ int   d_list[NE * NTOK];
__device__ int   d_cnt[NE];
__device__ float d_wgt[NPAIRS];
__device__ float d_probs[NTOK * NE];
__device__ float d_auxp[32 * NE];

// ---------------------------------------------------------------------------
// Helpers (generic PTX only)
// ---------------------------------------------------------------------------
__device__ __forceinline__ uint32_t smem_u32(const void* p) {
    uint32_t a;
    asm("{ .reg .u64 t; cvta.to.shared.u64 t, %1; cvt.u32.u64 %0, t; }" : "=r"(a) : "l"(p));
    return a;
}
__device__ __forceinline__ void cp16(uint32_t dst, const void* src) {
    asm volatile("cp.async.cg.shared.global [%0], [%1], 16;" :: "r"(dst), "l"(src));
}
#define CP_COMMIT() asm volatile("cp.async.commit_group;" ::: "memory")
#define CP_WAIT2()  asm volatile("cp.async.wait_group 2;" ::: "memory")

// Conflict-free swizzle for 64B rows of 16B chunks.
#define SWZ(r, c) ((uint32_t)((r) * 64 + (((c) ^ (((r) >> 1) & 3)) << 4)))

__device__ __forceinline__ void ldmA(uint32_t r[4], uint32_t addr) {
    asm volatile("ldmatrix.sync.aligned.m8n8.x4.shared.b16 {%0,%1,%2,%3}, [%4];"
                 : "=r"(r[0]), "=r"(r[1]), "=r"(r[2]), "=r"(r[3]) : "r"(addr));
}
__device__ __forceinline__ void ldmB(uint32_t r[2], uint32_t addr) {
    asm volatile("ldmatrix.sync.aligned.m8n8.x2.shared.b16 {%0,%1}, [%2];"
                 : "=r"(r[0]), "=r"(r[1]) : "r"(addr));
}
__device__ __forceinline__ void mma16816(float d[4], const uint32_t a[4], const uint32_t b[2]) {
    asm volatile("mma.sync.aligned.m16n8k16.row.col.f32.f16.f16.f32 "
                 "{%0,%1,%2,%3}, {%4,%5,%6,%7}, {%8,%9}, {%0,%1,%2,%3};"
                 : "+f"(d[0]), "+f"(d[1]), "+f"(d[2]), "+f"(d[3])
                 : "r"(a[0]), "r"(a[1]), "r"(a[2]), "r"(a[3]), "r"(b[0]), "r"(b[1]));
}
__device__ __forceinline__ uint32_t pack_h(__half a, __half b) {
    return (uint32_t)__half_as_ushort(a) | ((uint32_t)__half_as_ushort(b) << 16);
}
__device__ __forceinline__ float silu_mul(float g, float u) {
    return (g / (1.f + __expf(-g))) * u;
}

// ---------------------------------------------------------------------------
// Conversion + init fused: regions 0-2 = weights->fp16, region 3 = zero out.
// Also zeroes d_cnt (completes before router on the same stream).
// ---------------------------------------------------------------------------
struct ConvArgs {
    const float* src[3];
    __half* dst[3];
    float* out;
};

__global__ void conv4_kernel(ConvArgs a) {
    const int gid = blockIdx.x * blockDim.x + threadIdx.x;
    if (gid < NE) d_cnt[gid] = 0;
    const int total = 4 << 21;
    for (int i = gid; i < total; i += gridDim.x * blockDim.x) {
        const int reg = i >> 21;
        const int off = i & ((1 << 21) - 1);
        if (reg < 3) {
            float4 v = ((const float4*)a.src[reg])[off];
            uint32_t* h2 = (uint32_t*)a.dst[reg];
            h2[2 * off + 0] = pack_h(__float2half(v.x), __float2half(v.y));
            h2[2 * off + 1] = pack_h(__float2half(v.z), __float2half(v.w));
        } else {
            ((float4*)a.out)[off] = make_float4(0.f, 0.f, 0.f, 0.f);
        }
    }
}

// ---------------------------------------------------------------------------
// Router: logits/softmax/top-2 + emits x row as fp16
// ---------------------------------------------------------------------------
__global__ void router_kernel(const float* __restrict__ x, const float* __restrict__ gw) {
    const int lane = threadIdx.x & 31;
    const int warp = threadIdx.x >> 5;
    const int t = blockIdx.x * (blockDim.x >> 5) + warp;
    if (t >= NTOK) return;

    const float4* xp = (const float4*)(x + (size_t)t * D_MODEL);
    float4 xv[8];
#pragma unroll
    for (int i = 0; i < 8; i++) xv[i] = xp[i * 32 + lane];

    uint2* xo = (uint2*)(d_x + (size_t)t * D_MODEL);
#pragma unroll
    for (int i = 0; i < 8; i++)
        xo[i * 32 + lane] = make_uint2(pack_h(__float2half(xv[i].x), __float2half(xv[i].y)),
                                       pack_h(__float2half(xv[i].z), __float2half(xv[i].w)));

    float logit[NE];
#pragma unroll
    for (int e = 0; e < NE; e++) {
        const float4* gp = (const float4*)(gw + e * D_MODEL);
        float s = 0.f;
#pragma unroll
        for (int i = 0; i < 8; i++) {
            float4 g = gp[i * 32 + lane];
            s += xv[i].x * g.x + xv[i].y * g.y + xv[i].z * g.z + xv[i].w * g.w;
        }
#pragma unroll
        for (int o = 16; o > 0; o >>= 1) s += __shfl_xor_sync(0xffffffffu, s, o);
        logit[e] = s;
    }

    if (lane == 0) {
        float m = logit[0];
#pragma unroll
        for (int e = 1; e < NE; e++) m = fmaxf(m, logit[e]);
        float p[NE], sum = 0.f;
#pragma unroll
        for (int e = 0; e < NE; e++) { p[e] = expf(logit[e] - m); sum += p[e]; }
        const float inv = 1.f / sum;
#pragma unroll
        for (int e = 0; e < NE; e++) { p[e] *= inv; d_probs[t * NE + e] = p[e]; }

        int i0 = 0;
#pragma unroll
        for (int e = 1; e < NE; e++) if (p[e] > p[i0]) i0 = e;
        int i1 = (i0 == 0) ? 1 : 0;
#pragma unroll
        for (int e = 0; e < NE; e++) if (e != i0 && p[e] > p[i1]) i1 = e;

        const float s2 = p[i0] + p[i1];
        int pos0 = atomicAdd(&d_cnt[i0], 1);
        d_list[i0 * NTOK + pos0] = 2 * t;
        d_wgt[2 * t] = p[i0] / s2;
        int pos1 = atomicAdd(&d_cnt[i1], 1);
        d_list[i1 * NTOK + pos1] = 2 * t + 1;
        d_wgt[2 * t + 1] = p[i1] / s2;
    }
}

// ---------------------------------------------------------------------------
// Aux loss: 32-block partials + finalize (fixed-order, deterministic)
// ---------------------------------------------------------------------------
__global__ void aux_part_kernel() {
    __shared__ float s[256][NE];
    const int tid = threadIdx.x;
    const int t = blockIdx.x * 256 + tid;
#pragma unroll
    for (int e = 0; e < NE; e++) s[tid][e] = d_probs[t * NE + e];
    __syncthreads();
    const int w = tid >> 5, lane = tid & 31;
    if (w < NE) {
        float v = 0.f;
        for (int i = lane; i < 256; i += 32) v += s[i][w];
#pragma unroll
        for (int o = 16; o > 0; o >>= 1) v += __shfl_xor_sync(0xffffffffu, v, o);
        if (lane == 0) d_auxp[blockIdx.x * NE + w] = v;
    }
}

__global__ void aux_fin_kernel(float* __restrict__ out) {
    const int tid = threadIdx.x;
    __shared__ float ps[NE];
    if (tid < NE) {
        float v = 0.f;
        for (int b = 0; b < 32; b++) v += d_auxp[b * NE + tid];
        ps[tid] = v;
        out[(size_t)NTOK * D_MODEL + 1 + tid] = (float)d_cnt[tid];
    }
    __syncthreads();
    if (tid == 0) {
        float aux = 0.f;
        for (int e = 0; e < NE; e++)
            aux += ((float)d_cnt[e] * (1.f / (float)NPAIRS)) * (ps[e] * (1.f / (float)NTOK));
        out[(size_t)NTOK * D_MODEL] = (float)NE * aux;
    }
}

// ---------------------------------------------------------------------------
// GEMM1 fused (R8 config — best known): 512 threads, 4x4 warp grid,
// 32x32 warp tiles per matrix, 4-stage pipeline. Stage (24KB): A G U.
// ---------------------------------------------------------------------------
#define G1_STAGES 4
#define G1_STG  24576
#define G1_SMEM (1024 + G1_STAGES * G1_STG)

__device__ __forceinline__ void g1_issue(int tid, const int* plist,
                                         const __half* gw_, const __half* uw_,
                                         int n0, int kt, uint32_t base) {
    const int r = tid >> 2, c = tid & 3;
    const uint32_t sw = SWZ(r, c);
    const size_t aoff = (size_t)(plist[r] >> 1) * (D_MODEL * 2) + kt * 64 + c * 16;
    const size_t boff = (size_t)(n0 + r) * (D_MODEL * 2) + kt * 64 + c * 16;
    cp16(base + sw,         (const char*)d_x + aoff);
    cp16(base + 8192 + sw,  (const char*)gw_ + boff);
    cp16(base + 16384 + sw, (const char*)uw_ + boff);
}

__global__ __launch_bounds__(512, 1) void gemm1_kernel() {
    const int e = blockIdx.z;
    const int cnt = d_cnt[e];
    const int m0 = blockIdx.x * BM;
    if (m0 >= cnt) return;
    const int n0 = blockIdx.y * BN;

    extern __shared__ __align__(128) char smem[];
    const uint32_t sb = smem_u32(smem);
    const int tid = threadIdx.x;
    const int lane = tid & 31;
    const int w = tid >> 5;
    const int wm = w >> 2, wn = w & 3;
    const int rows = min(BM, cnt - m0);

    int* s_plist = (int*)smem;
    if (tid < BM) s_plist[tid] = (tid < rows) ? d_list[e * NTOK + m0 + tid] : 0;
    __syncthreads();

    const __half* gw_ = d_wg + ((size_t)e << 20);
    const __half* uw_ = d_wu + ((size_t)e << 20);

    g1_issue(tid, s_plist, gw_, uw_, n0, 0, sb + 1024);
    CP_COMMIT();
    g1_issue(tid, s_plist, gw_, uw_, n0, 1, sb + 1024 + G1_STG);
    CP_COMMIT();
    g1_issue(tid, s_plist, gw_, uw_, n0, 2, sb + 1024 + 2 * G1_STG);
    CP_COMMIT();

    float dg[2][4][4], du[2][4][4];
#pragma unroll
    for (int i = 0; i < 2; i++)
#pragma unroll
        for (int j = 0; j < 4; j++)
#pragma unroll
            for (int k = 0; k < 4; k++) { dg[i][j][k] = 0.f; du[i][j][k] = 0.f; }

    for (int kt = 0; kt < NKT; kt++) {
        CP_WAIT2();
        __syncthreads();
        if (kt + 3 < NKT)
            g1_issue(tid, s_plist, gw_, uw_, n0,
                     kt + 3, sb + 1024 + ((kt + 3) % G1_STAGES) * G1_STG);
        CP_COMMIT();

        const uint32_t st = sb + 1024 + (kt % G1_STAGES) * G1_STG;
#pragma unroll
        for (int ks = 0; ks < 2; ks++) {
            uint32_t ah[2][4];
#pragma unroll
            for (int i = 0; i < 2; i++) {
                const int row = wm * 32 + i * 16 + (lane & 15);
                const int ch = ks * 2 + (lane >> 4);
                ldmA(ah[i], st + SWZ(row, ch));
            }
            uint32_t bg[4][2], bu[4][2];
#pragma unroll
            for (int j = 0; j < 4; j++) {
                const int row = wn * 32 + j * 8 + (lane & 7);
                const int ch = ks * 2 + ((lane >> 3) & 1);
                const uint32_t off = SWZ(row, ch);
                ldmB(bg[j], st + 8192 + off);
                ldmB(bu[j], st + 16384 + off);
            }
#pragma unroll
            for (int i = 0; i < 2; i++)
#pragma unroll
                for (int j = 0; j < 4; j++) mma16816(dg[i][j], ah[i], bg[j]);
#pragma unroll
            for (int i = 0; i < 2; i++)
#pragma unroll
                for (int j = 0; j < 4; j++) mma16816(du[i][j], ah[i], bu[j]);
        }
        __syncthreads();
    }

    // Epilogue: act = silu(g)*u -> fp16
    const int r0 = lane >> 2;
    const int c0 = (lane & 3) * 2;
#pragma unroll
    for (int i = 0; i < 2; i++) {
        const int mA = wm * 32 + i * 16 + r0;
        const int mB = mA + 8;
        const int pidA = s_plist[mA & 127];
        const int pidB = s_plist[mB & 127];
#pragma unroll
        for (int j = 0; j < 4; j++) {
            const int col = n0 + wn * 32 + j * 8 + c0;
            if (mA < rows) {
                *(uint32_t*)(d_act + (size_t)pidA * D_FF + col) =
                    pack_h(__float2half(silu_mul(dg[i][j][0], du[i][j][0])),
                           __float2half(silu_mul(dg[i][j][1], du[i][j][1])));
            }
            if (mB < rows) {
                *(uint32_t*)(d_act + (size_t)pidB * D_FF + col) =
                    pack_h(__float2half(silu_mul(dg[i][j][2], du[i][j][2])),
                           __float2half(silu_mul(dg[i][j][3], du[i][j][3])));
            }
        }
    }
}

// ---------------------------------------------------------------------------
// GEMM2 (unchanged, known-good): 256 threads, 64x32 warp tiles, 4 stages,
// 2 CTAs/SM, float2 atomics.
// ---------------------------------------------------------------------------
#define G2_STAGES 4
#define G2_STG  16384
#define G2_SMEM (1024 + G2_STAGES * G2_STG)

__device__ __forceinline__ void g2_issue(int tid, const int* plist,
                                         const __half* bw, int n0, int kt, uint32_t base) {
#pragma unroll
    for (int q = 0; q < 2; q++) {
        const int id = tid + q * 256;
        const int r = id >> 2, c = id & 3;
        const uint32_t sw = SWZ(r, c);
        const size_t aoff = (size_t)plist[r] * (D_FF * 2) + kt * 64 + c * 16;
        const size_t boff = (size_t)(n0 + r) * (D_FF * 2) + kt * 64 + c * 16;
        cp16(base + sw,        (const char*)d_act + aoff);
        cp16(base + 8192 + sw, (const char*)bw + boff);
    }
}

__global__ __launch_bounds__(256, 2) void gemm2_kernel(float* __restrict__ out) {
    const int e = blockIdx.z;
    const int cnt = d_cnt[e];
    const int m0 = blockIdx.x * BM;
    if (m0 >= cnt) return;
    const int n0 = blockIdx.y * BN;

    extern __shared__ __align__(128) char smem[];
    const uint32_t sb = smem_u32(smem);
    const int tid = threadIdx.x;
    const int lane = tid & 31;
    const int w = tid >> 5;
    const int wm = w >> 2, wn = w & 3;
    const int rows = min(BM, cnt - m0);

    int* s_plist = (int*)smem;
    if (tid < BM) s_plist[tid] = (tid < rows) ? d_list[e * NTOK + m0 + tid] : 0;
    __syncthreads();

    const __half* bw = d_wd + ((size_t)e << 20);

    g2_issue(tid, s_plist, bw, n0, 0, sb + 1024);
    CP_COMMIT();
    g2_issue(tid, s_plist, bw, n0, 1, sb + 1024 + G2_STG);
    CP_COMMIT();
    g2_issue(tid, s_plist, bw, n0, 2, sb + 1024 + 2 * G2_STG);
    CP_COMMIT();

    float dd[4][4][4];
#pragma unroll
    for (int i = 0; i < 4; i++)
#pragma unroll
        for (int j = 0; j < 4; j++)
#pragma unroll
            for (int k = 0; k < 4; k++) dd[i][j][k] = 0.f;

    for (int kt = 0; kt < NKT; kt++) {
        CP_WAIT2();
        __syncthreads();
        if (kt + 3 < NKT)
            g2_issue(tid, s_plist, bw, n0, kt + 3,
                     sb + 1024 + ((kt + 3) % G2_STAGES) * G2_STG);
        CP_COMMIT();

        const uint32_t st = sb + 1024 + (kt % G2_STAGES) * G2_STG;
#pragma unroll
        for (int ks = 0; ks < 2; ks++) {
            uint32_t ah[4][4];
#pragma unroll
            for (int i = 0; i < 4; i++) {
                const int row = wm * 64 + i * 16 + (lane & 15);
                const int ch = ks * 2 + (lane >> 4);
                ldmA(ah[i], st + SWZ(row, ch));
            }
#pragma unroll
            for (int j = 0; j < 4; j++) {
                const int row = wn * 32 + j * 8 + (lane & 7);
                const int ch = ks * 2 + ((lane >> 3) & 1);
                uint32_t fb[2];
                ldmB(fb, st + 8192 + SWZ(row, ch));
#pragma unroll
                for (int i = 0; i < 4; i++) mma16816(dd[i][j], ah[i], fb);
            }
        }
        __syncthreads();
    }

    // Weighted deterministic scatter: float2 atomics (2 adds/element total)
    const int r0 = lane >> 2;
    const int c0 = (lane & 3) * 2;
#pragma unroll
    for (int i = 0; i < 4; i++) {
        const int mA = wm * 64 + i * 16 + r0;
        const int mB = mA + 8;
        const int pidA = s_plist[mA & 127];
        const int pidB = s_plist[mB & 127];
        const float wA = d_wgt[pidA];
        const float wB = d_wgt[pidB];
#pragma unroll
        for (int j = 0; j < 4; j++) {
            const int col = n0 + wn * 32 + j * 8 + c0;
            if (mA < rows) {
                float2* p = (float2*)(out + (size_t)(pidA >> 1) * D_MODEL + col);
                atomicAdd(p, make_float2(wA * dd[i][j][0], wA * dd[i][j][1]));
            }
            if (mB < rows) {
                float2* p = (float2*)(out + (size_t)(pidB >> 1) * D_MODEL + col);
                atomicAdd(p, make_float2(wB * dd[i][j][2], wB * dd[i][j][3]));
            }
        }
    }
}

// ---------------------------------------------------------------------------
// Launch
// ---------------------------------------------------------------------------
extern "C" void kernel_launch(void* const* d_in, const int* in_sizes, int n_in,
                              void* d_out, int out_size) {
    const float* x  = (const float*)d_in[0];
    const float* gw = (const float*)d_in[1];
    const float* wg = (const float*)d_in[2];
    const float* wu = (const float*)d_in[3];
    const float* wd = (const float*)d_in[4];
    float* out = (float*)d_out;

    cudaFuncSetAttribute(gemm1_kernel, cudaFuncAttributeMaxDynamicSharedMemorySize, G1_SMEM);
    cudaFuncSetAttribute(gemm2_kernel, cudaFuncAttributeMaxDynamicSharedMemorySize, G2_SMEM);

    ConvArgs ca;
    ca.src[0] = wg; ca.src[1] = wu; ca.src[2] = wd;
    cudaGetSymbolAddress((void**)&ca.dst[0], d_wg);
    cudaGetSymbolAddress((void**)&ca.dst[1], d_wu);
    cudaGetSymbolAddress((void**)&ca.dst[2], d_wd);
    ca.out = out;

    conv4_kernel<<<4736, 256>>>(ca);
    router_kernel<<<NTOK / 8, 256>>>(x, gw);
    aux_part_kernel<<<32, 256>>>();
    aux_fin_kernel<<<1, 64>>>(out);
    gemm1_kernel<<<dim3(64, 8, 8), 512, G1_SMEM>>>();
    gemm2_kernel<<<dim3(64, 8, 8), 256, G2_SMEM>>>(out);
}